// round 2
// baseline (speedup 1.0000x reference)
#include <cuda_runtime.h>
#include <cuda_bf16.h>
#include <cstdint>
#include <math.h>

// ---------------- problem constants ----------------
#define N_UTT   2000
#define NODES   6000
#define ND      200      // n_dim == nhidden
#define ND2     400      // 2*nhidden (variant=True support width)
#define HBW     256      // padded width of bf16 h buffer
#define MPAD    6048     // 63 * 96, padded adj rows
#define NLAYERS 8

// ---------------- device scratch (no allocation allowed) ----------------
static __device__ __nv_bfloat16 g_adjBF[(size_t)MPAD * NODES];   // 72.6 MB
static __device__ __nv_bfloat16 g_Hbf[(size_t)NODES * HBW];      // bf16 h, cols 200..255 zero
static __device__ float g_X [(size_t)NODES * ND];                // x (post-projection features)
static __device__ float g_H0[(size_t)NODES * ND];                // h0
static __device__ float g_Hf[(size_t)NODES * ND];                // current h (fp32)
static __device__ float g_SUP[(size_t)NODES * ND2];              // [hi | h0]

// ---------------- small PTX helpers ----------------
__device__ __forceinline__ void cp16(void* s, const void* g) {
    uint32_t sa = (uint32_t)__cvta_generic_to_shared(s);
    asm volatile("cp.async.cg.shared.global [%0], [%1], 16;\n" :: "r"(sa), "l"(g));
}
__device__ __forceinline__ void cp_commit() { asm volatile("cp.async.commit_group;\n" ::); }
__device__ __forceinline__ void cp_wait1()  { asm volatile("cp.async.wait_group 1;\n" ::); }
__device__ __forceinline__ void cp_wait0()  { asm volatile("cp.async.wait_group 0;\n" ::); }

__device__ __forceinline__ void ldsm_x4(uint32_t* r, const void* p) {
    uint32_t sa = (uint32_t)__cvta_generic_to_shared(p);
    asm volatile("ldmatrix.sync.aligned.m8n8.x4.shared.b16 {%0,%1,%2,%3}, [%4];\n"
                 : "=r"(r[0]), "=r"(r[1]), "=r"(r[2]), "=r"(r[3]) : "r"(sa));
}
__device__ __forceinline__ void ldsm_x4_t(uint32_t* r, const void* p) {
    uint32_t sa = (uint32_t)__cvta_generic_to_shared(p);
    asm volatile("ldmatrix.sync.aligned.m8n8.x4.trans.shared.b16 {%0,%1,%2,%3}, [%4];\n"
                 : "=r"(r[0]), "=r"(r[1]), "=r"(r[2]), "=r"(r[3]) : "r"(sa));
}
__device__ __forceinline__ void mma_bf16(float* c, const uint32_t* a, const uint32_t* b) {
    asm volatile("mma.sync.aligned.m16n8k16.row.col.f32.bf16.bf16.f32 "
                 "{%0,%1,%2,%3},{%4,%5,%6,%7},{%8,%9},{%0,%1,%2,%3};\n"
                 : "+f"(c[0]), "+f"(c[1]), "+f"(c[2]), "+f"(c[3])
                 : "r"(a[0]), "r"(a[1]), "r"(a[2]), "r"(a[3]), "r"(b[0]), "r"(b[1]));
}
__device__ __forceinline__ void mma_tf32(float* c, uint32_t a0, uint32_t a1, uint32_t a2,
                                         uint32_t a3, uint32_t b0, uint32_t b1) {
    asm volatile("mma.sync.aligned.m16n8k8.row.col.f32.tf32.tf32.f32 "
                 "{%0,%1,%2,%3},{%4,%5,%6,%7},{%8,%9},{%0,%1,%2,%3};\n"
                 : "+f"(c[0]), "+f"(c[1]), "+f"(c[2]), "+f"(c[3])
                 : "r"(a0), "r"(a1), "r"(a2), "r"(a3), "r"(b0), "r"(b1));
}
__device__ __forceinline__ uint32_t f2tf32(float x) {
    uint32_t r; asm("cvt.rna.tf32.f32 %0, %1;" : "=r"(r) : "f"(x)); return r;
}

// ---------------- adj fp32 -> bf16 (rows >= NODES zero-filled) ----------------
__global__ void k_conv_adj(const float* __restrict__ adj) {
    size_t i4 = (size_t)blockIdx.x * blockDim.x + threadIdx.x;
    size_t total = (size_t)MPAD * NODES / 4;
    if (i4 >= total) return;
    size_t e = i4 * 4;
    size_t r = e / NODES;           // NODES % 4 == 0 -> a float4 never crosses rows
    __nv_bfloat162 o01, o23;
    if (r < NODES) {
        float4 v = *reinterpret_cast<const float4*>(adj + e);
        o01 = __floats2bfloat162_rn(v.x, v.y);
        o23 = __floats2bfloat162_rn(v.z, v.w);
    } else {
        o01 = __floats2bfloat162_rn(0.f, 0.f);
        o23 = o01;
    }
    *reinterpret_cast<__nv_bfloat162*>(g_adjBF + e)     = o01;
    *reinterpret_cast<__nv_bfloat162*>(g_adjBF + e + 2) = o23;
}

// zero the padded columns (200..255) of g_Hbf once per launch (deterministic)
__global__ void k_zero_pad() {
    int i = blockIdx.x * blockDim.x + threadIdx.x;
    if (i < NODES * (HBW - ND)) {
        int r = i / (HBW - ND), c = ND + i % (HBW - ND);
        g_Hbf[(size_t)r * HBW + c] = __float2bfloat16(0.0f);
    }
}

// ---------------- GEMM1: SUP[:,0:200] = adjBF @ Hbf  (bf16 MMA, fp32 accum) ----------------
// grid (63, 2), 256 threads. BM=96, BN=128, BK=48.
#define G1_BM 96
#define G1_BN 128
#define G1_BK 48
__global__ __launch_bounds__(256) void k_gemm_adj() {
    __shared__ __nv_bfloat16 sA[2][G1_BM][56];   // 48 cols + 8 pad (112B rows)
    __shared__ __nv_bfloat16 sB[2][G1_BK][136];  // 128 cols + 8 pad (272B rows)

    const int tid  = threadIdx.x;
    const int lane = tid & 31;
    const int warp = tid >> 5;
    const int wm   = warp >> 2;      // 0..1 (48 rows each)
    const int wn   = warp & 3;       // 0..3 (32 cols each)
    const int bm0  = blockIdx.x * G1_BM;
    const int bn0  = blockIdx.y * G1_BN;

    float acc[3][4][4];
    #pragma unroll
    for (int i = 0; i < 3; i++)
        #pragma unroll
        for (int j = 0; j < 4; j++)
            #pragma unroll
            for (int k = 0; k < 4; k++) acc[i][j][k] = 0.f;

    auto load_tiles = [&](int st, int it) {
        const int k0 = it * G1_BK;
        for (int v = tid; v < (G1_BM * G1_BK / 8); v += 256) {   // 576 vec8
            int m = v / 6, kc = (v % 6) * 8;
            cp16(&sA[st][m][kc], g_adjBF + (size_t)(bm0 + m) * NODES + k0 + kc);
        }
        for (int v = tid; v < (G1_BK * G1_BN / 8); v += 256) {   // 768 vec8
            int k = v / 16, nc = (v % 16) * 8;
            cp16(&sB[st][k][nc], g_Hbf + (size_t)(k0 + k) * HBW + bn0 + nc);
        }
        cp_commit();
    };

    const int ITERS = NODES / G1_BK;   // 125
    load_tiles(0, 0);

    #pragma unroll 1
    for (int it = 0; it < ITERS; ++it) {
        if (it + 1 < ITERS) { load_tiles((it + 1) & 1, it + 1); cp_wait1(); }
        else                { cp_wait0(); }
        __syncthreads();
        const int st = it & 1;
        #pragma unroll
        for (int ks = 0; ks < 3; ks++) {
            uint32_t afr[3][4];
            #pragma unroll
            for (int mf = 0; mf < 3; mf++)
                ldsm_x4(afr[mf], &sA[st][wm * 48 + mf * 16 + (lane & 15)]
                                    [ks * 16 + ((lane >> 4) << 3)]);
            uint32_t bfr[4][2];
            #pragma unroll
            for (int nh = 0; nh < 2; nh++) {
                uint32_t r[4];
                ldsm_x4_t(r, &sB[st][ks * 16 + (lane & 15)]
                                    [wn * 32 + nh * 16 + ((lane >> 4) << 3)]);
                bfr[nh * 2][0] = r[0]; bfr[nh * 2][1] = r[1];
                bfr[nh * 2 + 1][0] = r[2]; bfr[nh * 2 + 1][1] = r[3];
            }
            #pragma unroll
            for (int mf = 0; mf < 3; mf++)
                #pragma unroll
                for (int nf = 0; nf < 4; nf++)
                    mma_bf16(acc[mf][nf], afr[mf], bfr[nf]);
        }
        __syncthreads();
    }

    // epilogue -> SUP[:,0:200]
    const int base_m = bm0 + wm * 48;
    const int base_n = bn0 + wn * 32;
    #pragma unroll
    for (int mf = 0; mf < 3; mf++)
        #pragma unroll
        for (int nf = 0; nf < 4; nf++) {
            int r = base_m + mf * 16 + (lane >> 2);
            int c = base_n + nf * 8 + ((lane & 3) << 1);
            float* a = acc[mf][nf];
            if (r < NODES) {
                if (c     < ND) g_SUP[(size_t)r * ND2 + c]     = a[0];
                if (c + 1 < ND) g_SUP[(size_t)r * ND2 + c + 1] = a[1];
            }
            int r2 = r + 8;
            if (r2 < NODES) {
                if (c     < ND) g_SUP[(size_t)r2 * ND2 + c]     = a[2];
                if (c + 1 < ND) g_SUP[(size_t)r2 * ND2 + c + 1] = a[3];
            }
        }
}

// ---------------- GEMM2: tf32 MMA, C = A[M,K] @ W[K,200], fused epilogues ----------------
// BM=64, BN=208 (full width), BK=16. 256 threads, warp tile 16x104.
// mode 0: X[row_off+m] = acc + bias
// mode 1: X[row_off+m] = acc + bias + spk_emb[argmax(qmask)]
// mode 2: h0 = relu(acc+bias) -> H0, SUP[:,200:400], Hbf
// mode 3: h  = relu(theta*acc + (1-theta)*(0.9*SUP[:,0:200] + 0.1*H0)) -> Hf, Hbf
#define G2_BM 64
#define G2_BN 208
#define G2_BK 16
__global__ __launch_bounds__(256) void k_gemm_tf32(
    const float* __restrict__ Aext, int asel, int lda, int M, int K,
    const float* __restrict__ W, const float* __restrict__ bias,
    int mode, float theta, int row_off,
    const float* __restrict__ qmask, const float* __restrict__ spk_emb)
{
    __shared__ uint32_t sAm[G2_BK][G2_BM + 1];   // [k][m]
    __shared__ uint32_t sBm[G2_BK][G2_BN + 1];   // [k][n]

    const float* A = (asel == 1) ? g_X : (asel == 2) ? g_SUP : Aext;

    const int tid  = threadIdx.x;
    const int lane = tid & 31;
    const int warp = tid >> 5;
    const int wm   = warp >> 1;   // 0..3
    const int wn   = warp & 1;    // 0..1
    const int bm0  = blockIdx.x * G2_BM;

    float acc[13][4];
    #pragma unroll
    for (int i = 0; i < 13; i++)
        #pragma unroll
        for (int j = 0; j < 4; j++) acc[i][j] = 0.f;

    const int ITERS = (K + G2_BK - 1) / G2_BK;
    for (int it = 0; it < ITERS; ++it) {
        const int k0 = it * G2_BK;
        __syncthreads();
        // load A tile (coalesced along k within a row)
        for (int v = tid; v < G2_BM * G2_BK; v += 256) {
            int k = v & 15, m = v >> 4;
            int gm = bm0 + m, gk = k0 + k;
            float val = (gm < M && gk < K) ? A[(size_t)gm * lda + gk] : 0.f;
            sAm[k][m] = f2tf32(val);
        }
        // load W tile (coalesced along n)
        for (int v = tid; v < G2_BK * G2_BN; v += 256) {
            int k = v / G2_BN, n = v % G2_BN;
            int gk = k0 + k;
            float val = (gk < K && n < ND) ? W[(size_t)gk * ND + n] : 0.f;
            sBm[k][n] = f2tf32(val);
        }
        __syncthreads();

        #pragma unroll
        for (int kb = 0; kb < G2_BK; kb += 8) {
            int mrow = wm * 16 + (lane >> 2);
            int kk   = kb + (lane & 3);
            uint32_t a0 = sAm[kk][mrow],     a1 = sAm[kk][mrow + 8];
            uint32_t a2 = sAm[kk + 4][mrow], a3 = sAm[kk + 4][mrow + 8];
            #pragma unroll
            for (int nf = 0; nf < 13; nf++) {
                int nc = wn * 104 + nf * 8 + (lane >> 2);
                uint32_t b0 = sBm[kb + (lane & 3)][nc];
                uint32_t b1 = sBm[kb + 4 + (lane & 3)][nc];
                mma_tf32(acc[nf], a0, a1, a2, a3, b0, b1);
            }
        }
    }

    // fused epilogue
    auto epi = [&](int m, int n, float v) {
        if (m >= M || n >= ND) return;
        if (mode == 0 || mode == 1) {
            float x = v + bias[n];
            if (mode == 1) {
                int b = m / 100, t = m % 100;
                float q0 = qmask[(t * 20 + b) * 2];
                float q1 = qmask[(t * 20 + b) * 2 + 1];
                int idx = (q1 > q0) ? 1 : 0;
                x += spk_emb[idx * ND + n];
            }
            g_X[(size_t)(row_off + m) * ND + n] = x;
        } else if (mode == 2) {
            float x = fmaxf(v + bias[n], 0.f);
            g_H0[(size_t)m * ND + n] = x;
            g_SUP[(size_t)m * ND2 + ND + n] = x;
            g_Hbf[(size_t)m * HBW + n] = __float2bfloat16(x);
        } else {  // mode 3
            float hi  = g_SUP[(size_t)m * ND2 + n];
            float h0v = g_H0[(size_t)m * ND + n];
            float x = theta * v + (1.f - theta) * (0.9f * hi + 0.1f * h0v);
            x = fmaxf(x, 0.f);
            g_Hf[(size_t)m * ND + n] = x;
            g_Hbf[(size_t)m * HBW + n] = __float2bfloat16(x);
        }
    };

    const int mloc = wm * 16 + (lane >> 2);
    #pragma unroll
    for (int nf = 0; nf < 13; nf++) {
        int c = wn * 104 + nf * 8 + ((lane & 3) << 1);
        epi(bm0 + mloc,     c,     acc[nf][0]);
        epi(bm0 + mloc,     c + 1, acc[nf][1]);
        epi(bm0 + mloc + 8, c,     acc[nf][2]);
        epi(bm0 + mloc + 8, c + 1, acc[nf][3]);
    }
}

// ---------------- output assembly: [2000, 1200] ----------------
__global__ void k_out(float* __restrict__ out) {
    int i = blockIdx.x * blockDim.x + threadIdx.x;
    if (i >= N_UTT * 1200) return;
    int r = i / 1200, c = i % 1200;
    int seg = c / ND, cc = c % ND;
    int chunk = seg >> 1;
    const float* src = (seg & 1) ? g_Hf : g_X;
    out[i] = src[(size_t)(chunk * N_UTT + r) * ND + cc];
}

// ---------------- launch ----------------
extern "C" void kernel_launch(void* const* d_in, const int* in_sizes, int n_in,
                              void* d_out, int out_size) {
    const float* a    = (const float*)d_in[0];
    const float* v    = (const float*)d_in[1];
    const float* l    = (const float*)d_in[2];
    const float* qm   = (const float*)d_in[3];
    const float* adj  = (const float*)d_in[4];
    const float* Wa   = (const float*)d_in[5];
    const float* ba   = (const float*)d_in[6];
    const float* Wv   = (const float*)d_in[7];
    const float* bv   = (const float*)d_in[8];
    const float* Wl   = (const float*)d_in[9];
    const float* bl   = (const float*)d_in[10];
    const float* spk  = (const float*)d_in[11];
    const float* W0   = (const float*)d_in[12];
    const float* b0   = (const float*)d_in[13];
    const float* convW= (const float*)d_in[14];
    float* out = (float*)d_out;

    // 1. adj -> bf16 (padded rows zero-filled)
    {
        size_t total4 = (size_t)MPAD * NODES / 4;
        k_conv_adj<<<(unsigned)((total4 + 255) / 256), 256>>>(adj);
    }
    k_zero_pad<<<(NODES * (HBW - ND) + 255) / 256, 256>>>();

    // 2. modality projections -> X
    k_gemm_tf32<<<(N_UTT + G2_BM - 1) / G2_BM, 256>>>(a, 0, 300,  N_UTT, 300,  Wa, ba, 0, 0.f, 0,    nullptr, nullptr);
    k_gemm_tf32<<<(N_UTT + G2_BM - 1) / G2_BM, 256>>>(v, 0, 342,  N_UTT, 342,  Wv, bv, 0, 0.f, 2000, nullptr, nullptr);
    k_gemm_tf32<<<(N_UTT + G2_BM - 1) / G2_BM, 256>>>(l, 0, 1024, N_UTT, 1024, Wl, bl, 1, 0.f, 4000, qm, spk);

    // 3. h0 = relu(X @ W0 + b0) -> H0, SUP[:,200:400], Hbf
    k_gemm_tf32<<<(NODES + G2_BM - 1) / G2_BM, 256>>>(nullptr, 1, ND, NODES, ND, W0, b0, 2, 0.f, 0, nullptr, nullptr);

    // 4. GCNII layers
    for (int k = 0; k < NLAYERS; ++k) {
        float theta = logf(0.5f / (float)(k + 1) + 1.0f);
        dim3 g1(MPAD / G1_BM, 2);
        k_gemm_adj<<<g1, 256>>>();
        k_gemm_tf32<<<(NODES + G2_BM - 1) / G2_BM, 256>>>(
            nullptr, 2, ND2, NODES, ND2, convW + (size_t)k * ND2 * ND,
            nullptr, 3, theta, 0, nullptr, nullptr);
    }

    // 5. gather output
    k_out<<<(N_UTT * 1200 + 255) / 256, 256>>>(out);
}